// round 14
// baseline (speedup 1.0000x reference)
#include <cuda_runtime.h>
#include <stdint.h>

// BurgerDissipativeLossOperator — k_du eliminated.
//
//   du[i]  = (u1[i]*A[i] - B[i]) / max(cnt[i],1)   A=Σ 1/len, B=Σ u1[src]/len
//   d2u[i] = (du[i]*A[i] - C[i]) / max(cnt[i],1)   C=Σ du[src]/len
//   loss   = ((u0-u1)/dt + du*u1 - MU*d2u) * mask
//
// g_acc[i] = {V, B, u1, pad} (V = 256*cnt + A packs cnt and A):
//   pass 1: gather x_t1[2s] (read-only array), red.v2 {V,B} into g_acc[d]
//   pass 2: 16B read-only gather of g_acc[s] (ONE 32B sector), du computed
//           inline, scalar atomic into separate g_C[d]
// Rules from R3/R10: per pass, the gathered array is never the RMW array.
// k_du (80MB + launch) is deleted; k_final recomputes du from g_acc.

#define N_NODES 4000000
#define N_EDGES 8000000
#define INV_DT  100.0f
#define MU      0.01f
#define K_PACK  256.0f
#define INV_K   0.00390625f   // 1/256

__device__ float4 g_acc[N_NODES];   // {V, B, u1, pad}
__device__ float  g_C[N_NODES];     // Σ du[src]/len

// unpack V and compute du (fast reciprocal)
__device__ __forceinline__ float node_du(float V, float B, float u1,
                                         float& A, float& rc) {
    float k = floorf(V * INV_K);          // cnt
    A  = V - K_PACK * k;
    rc = __fdividef(1.0f, fmaxf(k, 1.0f));
    return (u1 * A - B) * rc;
}

// ---------------------------------------------------------------------------
// init (4 nodes/thread): g_acc = {0,0,u1,0}, g_C = 0
__global__ void __launch_bounds__(256) k_init(const float4* __restrict__ x_t1) {
    int t = blockIdx.x * blockDim.x + threadIdx.x;
    if (t >= N_NODES / 4) return;
    float4 a = __ldcs(&x_t1[t * 2 + 0]);   // u1[4t],v,u1[4t+1],v
    float4 b = __ldcs(&x_t1[t * 2 + 1]);   // u1[4t+2],v,u1[4t+3],v
    int i = t * 4;
    g_acc[i + 0] = make_float4(0.f, 0.f, a.x, 0.f);
    g_acc[i + 1] = make_float4(0.f, 0.f, a.z, 0.f);
    g_acc[i + 2] = make_float4(0.f, 0.f, b.x, 0.f);
    g_acc[i + 3] = make_float4(0.f, 0.f, b.z, 0.f);
    ((float4*)g_C)[t] = make_float4(0.f, 0.f, 0.f, 0.f);
}

// pass 1 (4 edges/thread): gather x_t1[2s]; red.v2 {V += 256+1/len, B += u1[s]/len}
__global__ void __launch_bounds__(256) k_edge1(const int4* __restrict__ ei_s,
                                               const int4* __restrict__ ei_d,
                                               const float4* __restrict__ attr,
                                               const float* __restrict__ x_t1) {
    int t = blockIdx.x * blockDim.x + threadIdx.x;
    if (t >= N_EDGES / 4) return;
    int4   s4 = __ldcs(&ei_s[t]);
    int4   d4 = __ldcs(&ei_d[t]);
    float4 l4 = __ldcs(&attr[t]);

    float u0 = __ldg(&x_t1[2 * s4.x]);
    float u1 = __ldg(&x_t1[2 * s4.y]);
    float u2 = __ldg(&x_t1[2 * s4.z]);
    float u3 = __ldg(&x_t1[2 * s4.w]);

    float r0 = __fdividef(1.0f, l4.x);
    float r1 = __fdividef(1.0f, l4.y);
    float r2 = __fdividef(1.0f, l4.z);
    float r3 = __fdividef(1.0f, l4.w);

    asm volatile("red.global.add.v2.f32 [%0], {%1, %2};"
                 :: "l"(&g_acc[d4.x]), "f"(K_PACK + r0), "f"(u0 * r0) : "memory");
    asm volatile("red.global.add.v2.f32 [%0], {%1, %2};"
                 :: "l"(&g_acc[d4.y]), "f"(K_PACK + r1), "f"(u1 * r1) : "memory");
    asm volatile("red.global.add.v2.f32 [%0], {%1, %2};"
                 :: "l"(&g_acc[d4.z]), "f"(K_PACK + r2), "f"(u2 * r2) : "memory");
    asm volatile("red.global.add.v2.f32 [%0], {%1, %2};"
                 :: "l"(&g_acc[d4.w]), "f"(K_PACK + r3), "f"(u3 * r3) : "memory");
}

// pass 2 (4 edges/thread): gather g_acc[s] (read-only here, one sector),
// compute du_src inline, C[d] += du_src/len into separate g_C
__global__ void __launch_bounds__(256) k_edge2(const int4* __restrict__ ei_s,
                                               const int4* __restrict__ ei_d,
                                               const float4* __restrict__ attr) {
    int t = blockIdx.x * blockDim.x + threadIdx.x;
    if (t >= N_EDGES / 4) return;
    int4   s4 = __ldcs(&ei_s[t]);
    int4   d4 = __ldcs(&ei_d[t]);
    float4 l4 = __ldcs(&attr[t]);

    float4 a0 = __ldg(&g_acc[s4.x]);
    float4 a1 = __ldg(&g_acc[s4.y]);
    float4 a2 = __ldg(&g_acc[s4.z]);
    float4 a3 = __ldg(&g_acc[s4.w]);

    float A, rc;
    float du0 = node_du(a0.x, a0.y, a0.z, A, rc);
    float du1 = node_du(a1.x, a1.y, a1.z, A, rc);
    float du2 = node_du(a2.x, a2.y, a2.z, A, rc);
    float du3 = node_du(a3.x, a3.y, a3.z, A, rc);

    atomicAdd(&g_C[d4.x], du0 * __fdividef(1.0f, l4.x));
    atomicAdd(&g_C[d4.y], du1 * __fdividef(1.0f, l4.y));
    atomicAdd(&g_C[d4.z], du2 * __fdividef(1.0f, l4.z));
    atomicAdd(&g_C[d4.w], du3 * __fdividef(1.0f, l4.w));
}

// epilogue (4 nodes/thread): du/d2u/loss from g_acc + g_C + inputs
__device__ __forceinline__ float node_loss(float4 a, float C, float u0, float m) {
    float A, rc;
    float du  = node_du(a.x, a.y, a.z, A, rc);
    float d2u = (du * A - C) * rc;
    return ((u0 - a.z) * INV_DT + du * a.z - MU * d2u) * m;
}

__global__ void __launch_bounds__(256) k_final(const float4* __restrict__ x_t,
                                               const float4* __restrict__ mask,
                                               float4* __restrict__ out) {
    int t = blockIdx.x * blockDim.x + threadIdx.x;
    if (t >= N_NODES / 4) return;
    int i = t * 4;
    float4 a0 = g_acc[i + 0];
    float4 a1 = g_acc[i + 1];
    float4 a2 = g_acc[i + 2];
    float4 a3 = g_acc[i + 3];
    float4 C  = ((const float4*)g_C)[t];
    float4 xa = __ldcs(&x_t[t * 2 + 0]);
    float4 xb = __ldcs(&x_t[t * 2 + 1]);
    float4 m  = __ldcs(&mask[t]);

    float4 o;
    o.x = node_loss(a0, C.x, xa.x, m.x);
    o.y = node_loss(a1, C.y, xa.z, m.y);
    o.z = node_loss(a2, C.z, xb.x, m.z);
    o.w = node_loss(a3, C.w, xb.z, m.w);
    __stcs(&out[t], o);
}

// ---------------------------------------------------------------------------
extern "C" void kernel_launch(void* const* d_in, const int* in_sizes, int n_in,
                              void* d_out, int out_size) {
    const float4* x_t   = (const float4*)d_in[0];
    const float*  x_t1  = (const float*)d_in[1];
    const float4* x_t1v = (const float4*)d_in[1];
    const int*    ei    = (const int*)d_in[2];
    const float4* attr  = (const float4*)d_in[3];
    const float4* mask  = (const float4*)d_in[4];
    float4*       out   = (float4*)d_out;

    const int4* ei_s = (const int4*)ei;
    const int4* ei_d = (const int4*)(ei + N_EDGES);

    const int TB = 256;
    const int gn = (N_NODES / 4 + TB - 1) / TB;
    const int ge = (N_EDGES / 4 + TB - 1) / TB;

    k_init <<<gn, TB>>>(x_t1v);
    k_edge1<<<ge, TB>>>(ei_s, ei_d, attr, x_t1);
    k_edge2<<<ge, TB>>>(ei_s, ei_d, attr);
    k_final<<<gn, TB>>>(x_t, mask, out);
}

// round 15
// speedup vs baseline: 1.1573x; 1.1573x over previous
#include <cuda_runtime.h>
#include <stdint.h>

// BurgerDissipativeLossOperator — R12 configuration (empirical optimum).
//
//   du[i]  = (u1[i]*A[i] - B[i]) / max(cnt[i],1)   A=Σ 1/len, B=Σ u1[src]/len
//   d2u[i] = (du[i]*A[i] - C[i]) / max(cnt[i],1)   C=Σ du[src]/len
//   loss   = ((u0-u1)/dt + du*u1 - MU*d2u) * mask
//
// V = Σ (256 + 1/len) = 256*cnt + A packs cnt+A into one float ->
// pass 1 is a single red.global.add.v2.f32 {V,B} per edge (8B RMW).
// Design laws (R3/R10/R14): per pass the gathered array is read-only and
// compact (≤16MB); RMW accumulators are separate and ≤8B/node. Edge passes
// run at ~86% of the LTS cap (1 gather sector + 1 RMW sector + 12B streams
// per edge — irreducible for an unsorted edge list).

#define N_NODES 4000000
#define N_EDGES 8000000
#define INV_DT  100.0f
#define MU      0.01f
#define K_PACK  256.0f
#define INV_K   0.00390625f   // 1/256

__device__ float2 g_acc[N_NODES];   // {V = 256*cnt + A, B}
__device__ float  g_C[N_NODES];     // Σ du[src]/len
__device__ float  g_du[N_NODES];    // written by k_du, gathered by k_edge2
__device__ float  g_u1[N_NODES];    // compacted x_t1[:,0]

// unpack V and compute du (fast reciprocal)
__device__ __forceinline__ float node_du(float V, float B, float u1,
                                         float& A, float& rc) {
    float k = floorf(V * INV_K);          // cnt
    A  = V - K_PACK * k;
    rc = __fdividef(1.0f, fmaxf(k, 1.0f));
    return (u1 * A - B) * rc;
}

// ---------------------------------------------------------------------------
// init (4 nodes/thread): zero accumulators, compact u1
__global__ void __launch_bounds__(256) k_init(const float4* __restrict__ x_t1) {
    int t = blockIdx.x * blockDim.x + threadIdx.x;
    if (t >= N_NODES / 4) return;
    float4 z = make_float4(0.f, 0.f, 0.f, 0.f);
    ((float4*)g_acc)[t * 2 + 0] = z;
    ((float4*)g_acc)[t * 2 + 1] = z;
    ((float4*)g_C)[t] = z;
    float4 a = __ldcs(&x_t1[t * 2 + 0]);
    float4 b = __ldcs(&x_t1[t * 2 + 1]);
    ((float4*)g_u1)[t] = make_float4(a.x, a.z, b.x, b.z);
}

// pass 1 (4 edges/thread): red.v2 {V += 256 + 1/len, B += u1[s]/len}
__global__ void __launch_bounds__(256) k_edge1(const int4* __restrict__ ei_s,
                                               const int4* __restrict__ ei_d,
                                               const float4* __restrict__ attr) {
    int t = blockIdx.x * blockDim.x + threadIdx.x;
    if (t >= N_EDGES / 4) return;
    int4   s4 = __ldcs(&ei_s[t]);
    int4   d4 = __ldcs(&ei_d[t]);
    float4 l4 = __ldcs(&attr[t]);

    float u0 = __ldg(&g_u1[s4.x]);
    float u1 = __ldg(&g_u1[s4.y]);
    float u2 = __ldg(&g_u1[s4.z]);
    float u3 = __ldg(&g_u1[s4.w]);

    float r0 = __fdividef(1.0f, l4.x);
    float r1 = __fdividef(1.0f, l4.y);
    float r2 = __fdividef(1.0f, l4.z);
    float r3 = __fdividef(1.0f, l4.w);

    asm volatile("red.global.add.v2.f32 [%0], {%1, %2};"
                 :: "l"(&g_acc[d4.x]), "f"(K_PACK + r0), "f"(u0 * r0) : "memory");
    asm volatile("red.global.add.v2.f32 [%0], {%1, %2};"
                 :: "l"(&g_acc[d4.y]), "f"(K_PACK + r1), "f"(u1 * r1) : "memory");
    asm volatile("red.global.add.v2.f32 [%0], {%1, %2};"
                 :: "l"(&g_acc[d4.z]), "f"(K_PACK + r2), "f"(u2 * r2) : "memory");
    asm volatile("red.global.add.v2.f32 [%0], {%1, %2};"
                 :: "l"(&g_acc[d4.w]), "f"(K_PACK + r3), "f"(u3 * r3) : "memory");
}

// node pass (4 nodes/thread): du = (u1*A - B) / max(cnt,1)
__global__ void __launch_bounds__(256) k_du() {
    int t = blockIdx.x * blockDim.x + threadIdx.x;
    if (t >= N_NODES / 4) return;
    float4 u  = ((const float4*)g_u1)[t];
    float4 p0 = ((const float4*)g_acc)[t * 2 + 0];  // {V0,B0,V1,B1}
    float4 p1 = ((const float4*)g_acc)[t * 2 + 1];  // {V2,B2,V3,B3}
    float A, rc;
    float4 du;
    du.x = node_du(p0.x, p0.y, u.x, A, rc);
    du.y = node_du(p0.z, p0.w, u.y, A, rc);
    du.z = node_du(p1.x, p1.y, u.z, A, rc);
    du.w = node_du(p1.z, p1.w, u.w, A, rc);
    ((float4*)g_du)[t] = du;
}

// pass 2 (4 edges/thread): C[d] += du[s]/len
__global__ void __launch_bounds__(256) k_edge2(const int4* __restrict__ ei_s,
                                               const int4* __restrict__ ei_d,
                                               const float4* __restrict__ attr) {
    int t = blockIdx.x * blockDim.x + threadIdx.x;
    if (t >= N_EDGES / 4) return;
    int4   s4 = __ldcs(&ei_s[t]);
    int4   d4 = __ldcs(&ei_d[t]);
    float4 l4 = __ldcs(&attr[t]);

    float d0 = __ldg(&g_du[s4.x]);
    float d1 = __ldg(&g_du[s4.y]);
    float d2 = __ldg(&g_du[s4.z]);
    float d3 = __ldg(&g_du[s4.w]);

    atomicAdd(&g_C[d4.x], d0 * __fdividef(1.0f, l4.x));
    atomicAdd(&g_C[d4.y], d1 * __fdividef(1.0f, l4.y));
    atomicAdd(&g_C[d4.z], d2 * __fdividef(1.0f, l4.z));
    atomicAdd(&g_C[d4.w], d3 * __fdividef(1.0f, l4.w));
}

// epilogue (4 nodes/thread): recompute du from {V,B,u1}; no g_du read
__device__ __forceinline__ float node_loss(float V, float B, float C,
                                           float u0, float u1, float m) {
    float A, rc;
    float du  = node_du(V, B, u1, A, rc);
    float d2u = (du * A - C) * rc;
    return ((u0 - u1) * INV_DT + du * u1 - MU * d2u) * m;
}

__global__ void __launch_bounds__(256) k_final(const float4* __restrict__ x_t,
                                               const float4* __restrict__ mask,
                                               float4* __restrict__ out) {
    int t = blockIdx.x * blockDim.x + threadIdx.x;
    if (t >= N_NODES / 4) return;
    float4 p0 = ((const float4*)g_acc)[t * 2 + 0];
    float4 p1 = ((const float4*)g_acc)[t * 2 + 1];
    float4 C  = ((const float4*)g_C)[t];
    float4 u1 = ((const float4*)g_u1)[t];
    float4 xa = __ldcs(&x_t[t * 2 + 0]);
    float4 xb = __ldcs(&x_t[t * 2 + 1]);
    float4 m  = __ldcs(&mask[t]);

    float4 o;
    o.x = node_loss(p0.x, p0.y, C.x, xa.x, u1.x, m.x);
    o.y = node_loss(p0.z, p0.w, C.y, xa.z, u1.y, m.y);
    o.z = node_loss(p1.x, p1.y, C.z, xb.x, u1.z, m.z);
    o.w = node_loss(p1.z, p1.w, C.w, xb.z, u1.w, m.w);
    __stcs(&out[t], o);
}

// ---------------------------------------------------------------------------
extern "C" void kernel_launch(void* const* d_in, const int* in_sizes, int n_in,
                              void* d_out, int out_size) {
    const float4* x_t  = (const float4*)d_in[0];
    const float4* x_t1 = (const float4*)d_in[1];
    const int*    ei   = (const int*)d_in[2];
    const float4* attr = (const float4*)d_in[3];
    const float4* mask = (const float4*)d_in[4];
    float4*       out  = (float4*)d_out;

    const int4* ei_s = (const int4*)ei;
    const int4* ei_d = (const int4*)(ei + N_EDGES);

    const int TB = 256;
    const int gn = (N_NODES / 4 + TB - 1) / TB;
    const int ge = (N_EDGES / 4 + TB - 1) / TB;

    k_init <<<gn, TB>>>(x_t1);
    k_edge1<<<ge, TB>>>(ei_s, ei_d, attr);
    k_du   <<<gn, TB>>>();
    k_edge2<<<ge, TB>>>(ei_s, ei_d, attr);
    k_final<<<gn, TB>>>(x_t, mask, out);
}

// round 16
// speedup vs baseline: 1.2121x; 1.0473x over previous
#include <cuda_runtime.h>
#include <stdint.h>

// BurgerDissipativeLossOperator — init-free formulation.
//
//   du[i]  = (u1[i]*A[i] - B[i]) / max(cnt[i],1)   A=Σ 1/len, B=Σ u1[src]/len
//   d2u[i] = (du[i]*A[i] - C[i]) / max(cnt[i],1)   C=Σ du[src]/len
//   loss   = ((u0-u1)/dt + du*u1 - MU*d2u) * mask
//
// V = Σ (256 + 1/len) = 256*cnt + A packs cnt+A into one float ->
// pass 1 is a single red.global.add.v2.f32 {V,B} per edge (8B RMW).
//
// ZERO-INVARIANT: __device__ globals are zero-initialized at module load,
// and k_final restores g_acc/g_C to zero after consuming them (each thread
// zeroes exactly the elements it read). So the accumulators are all-zero at
// every kernel_launch entry — k_init is deleted (-96MB, -1 launch).
// Deterministic: same inputs -> same work -> same output on every call.
//
// Design laws (R3/R10/R14): per pass the gathered array is read-only and
// compact; RMW accumulators are separate and ≤8B/node.

#define N_NODES 4000000
#define N_EDGES 8000000
#define INV_DT  100.0f
#define MU      0.01f
#define K_PACK  256.0f
#define INV_K   0.00390625f   // 1/256

__device__ float2 g_acc[N_NODES];   // {V = 256*cnt + A, B}  (zero at entry)
__device__ float  g_C[N_NODES];     // Σ du[src]/len          (zero at entry)
__device__ float  g_du[N_NODES];    // written by k_du, gathered by k_edge2

// unpack V and compute du (fast reciprocal)
__device__ __forceinline__ float node_du(float V, float B, float u1,
                                         float& A, float& rc) {
    float k = floorf(V * INV_K);          // cnt
    A  = V - K_PACK * k;
    rc = __fdividef(1.0f, fmaxf(k, 1.0f));
    return (u1 * A - B) * rc;
}

// ---------------------------------------------------------------------------
// pass 1 (4 edges/thread): gather x_t1[2s]; red.v2 {V += 256+1/len, B += u1[s]/len}
__global__ void __launch_bounds__(256) k_edge1(const int4* __restrict__ ei_s,
                                               const int4* __restrict__ ei_d,
                                               const float4* __restrict__ attr,
                                               const float* __restrict__ x_t1) {
    int t = blockIdx.x * blockDim.x + threadIdx.x;
    if (t >= N_EDGES / 4) return;
    int4   s4 = __ldcs(&ei_s[t]);
    int4   d4 = __ldcs(&ei_d[t]);
    float4 l4 = __ldcs(&attr[t]);

    float u0 = __ldg(&x_t1[2 * s4.x]);
    float u1 = __ldg(&x_t1[2 * s4.y]);
    float u2 = __ldg(&x_t1[2 * s4.z]);
    float u3 = __ldg(&x_t1[2 * s4.w]);

    float r0 = __fdividef(1.0f, l4.x);
    float r1 = __fdividef(1.0f, l4.y);
    float r2 = __fdividef(1.0f, l4.z);
    float r3 = __fdividef(1.0f, l4.w);

    asm volatile("red.global.add.v2.f32 [%0], {%1, %2};"
                 :: "l"(&g_acc[d4.x]), "f"(K_PACK + r0), "f"(u0 * r0) : "memory");
    asm volatile("red.global.add.v2.f32 [%0], {%1, %2};"
                 :: "l"(&g_acc[d4.y]), "f"(K_PACK + r1), "f"(u1 * r1) : "memory");
    asm volatile("red.global.add.v2.f32 [%0], {%1, %2};"
                 :: "l"(&g_acc[d4.z]), "f"(K_PACK + r2), "f"(u2 * r2) : "memory");
    asm volatile("red.global.add.v2.f32 [%0], {%1, %2};"
                 :: "l"(&g_acc[d4.w]), "f"(K_PACK + r3), "f"(u3 * r3) : "memory");
}

// node pass (4 nodes/thread): du = (u1*A - B) / max(cnt,1)
__global__ void __launch_bounds__(256) k_du(const float4* __restrict__ x_t1) {
    int t = blockIdx.x * blockDim.x + threadIdx.x;
    if (t >= N_NODES / 4) return;
    float4 xa = __ldg(&x_t1[t * 2 + 0]);   // u1[4t],v,u1[4t+1],v
    float4 xb = __ldg(&x_t1[t * 2 + 1]);   // u1[4t+2],v,u1[4t+3],v
    float4 p0 = ((const float4*)g_acc)[t * 2 + 0];  // {V0,B0,V1,B1}
    float4 p1 = ((const float4*)g_acc)[t * 2 + 1];  // {V2,B2,V3,B3}
    float A, rc;
    float4 du;
    du.x = node_du(p0.x, p0.y, xa.x, A, rc);
    du.y = node_du(p0.z, p0.w, xa.z, A, rc);
    du.z = node_du(p1.x, p1.y, xb.x, A, rc);
    du.w = node_du(p1.z, p1.w, xb.z, A, rc);
    ((float4*)g_du)[t] = du;
}

// pass 2 (4 edges/thread): C[d] += du[s]/len
__global__ void __launch_bounds__(256) k_edge2(const int4* __restrict__ ei_s,
                                               const int4* __restrict__ ei_d,
                                               const float4* __restrict__ attr) {
    int t = blockIdx.x * blockDim.x + threadIdx.x;
    if (t >= N_EDGES / 4) return;
    int4   s4 = __ldcs(&ei_s[t]);
    int4   d4 = __ldcs(&ei_d[t]);
    float4 l4 = __ldcs(&attr[t]);

    float d0 = __ldg(&g_du[s4.x]);
    float d1 = __ldg(&g_du[s4.y]);
    float d2 = __ldg(&g_du[s4.z]);
    float d3 = __ldg(&g_du[s4.w]);

    atomicAdd(&g_C[d4.x], d0 * __fdividef(1.0f, l4.x));
    atomicAdd(&g_C[d4.y], d1 * __fdividef(1.0f, l4.y));
    atomicAdd(&g_C[d4.z], d2 * __fdividef(1.0f, l4.z));
    atomicAdd(&g_C[d4.w], d3 * __fdividef(1.0f, l4.w));
}

// epilogue (4 nodes/thread): compute loss, then RESTORE ZEROS in g_acc/g_C
__device__ __forceinline__ float node_loss(float V, float B, float C,
                                           float u0, float u1, float m) {
    float A, rc;
    float du  = node_du(V, B, u1, A, rc);
    float d2u = (du * A - C) * rc;
    return ((u0 - u1) * INV_DT + du * u1 - MU * d2u) * m;
}

__global__ void __launch_bounds__(256) k_final(const float4* __restrict__ x_t,
                                               const float4* __restrict__ x_t1,
                                               const float4* __restrict__ mask,
                                               float4* __restrict__ out) {
    int t = blockIdx.x * blockDim.x + threadIdx.x;
    if (t >= N_NODES / 4) return;
    float4 p0 = ((const float4*)g_acc)[t * 2 + 0];
    float4 p1 = ((const float4*)g_acc)[t * 2 + 1];
    float4 C  = ((const float4*)g_C)[t];
    float4 ya = __ldg(&x_t1[t * 2 + 0]);
    float4 yb = __ldg(&x_t1[t * 2 + 1]);
    float4 xa = __ldcs(&x_t[t * 2 + 0]);
    float4 xb = __ldcs(&x_t[t * 2 + 1]);
    float4 m  = __ldcs(&mask[t]);

    float4 o;
    o.x = node_loss(p0.x, p0.y, C.x, xa.x, ya.x, m.x);
    o.y = node_loss(p0.z, p0.w, C.y, xa.z, ya.z, m.y);
    o.z = node_loss(p1.x, p1.y, C.z, xb.x, yb.x, m.z);
    o.w = node_loss(p1.z, p1.w, C.w, xb.z, yb.z, m.w);
    __stcs(&out[t], o);

    // restore the zero-invariant for the next launch (exactly the elements
    // this thread consumed; no cross-thread hazard)
    float4 z = make_float4(0.f, 0.f, 0.f, 0.f);
    ((float4*)g_acc)[t * 2 + 0] = z;
    ((float4*)g_acc)[t * 2 + 1] = z;
    ((float4*)g_C)[t] = z;
}

// ---------------------------------------------------------------------------
extern "C" void kernel_launch(void* const* d_in, const int* in_sizes, int n_in,
                              void* d_out, int out_size) {
    const float4* x_t   = (const float4*)d_in[0];
    const float*  x_t1  = (const float*)d_in[1];
    const float4* x_t1v = (const float4*)d_in[1];
    const int*    ei    = (const int*)d_in[2];
    const float4* attr  = (const float4*)d_in[3];
    const float4* mask  = (const float4*)d_in[4];
    float4*       out   = (float4*)d_out;

    const int4* ei_s = (const int4*)ei;
    const int4* ei_d = (const int4*)(ei + N_EDGES);

    const int TB = 256;
    const int gn = (N_NODES / 4 + TB - 1) / TB;
    const int ge = (N_EDGES / 4 + TB - 1) / TB;

    k_edge1<<<ge, TB>>>(ei_s, ei_d, attr, x_t1);
    k_du   <<<gn, TB>>>(x_t1v);
    k_edge2<<<ge, TB>>>(ei_s, ei_d, attr);
    k_final<<<gn, TB>>>(x_t, x_t1v, mask, out);
}